// round 7
// baseline (speedup 1.0000x reference)
#include <cuda_runtime.h>
#include <cuda_fp16.h>
#include <cstdint>
#include <cstddef>

// Problem constants.
#define NEXP 16
#define NTOK 2048
#define DIM  1024
#define HID  4096

// Static device scratch (no runtime allocation).
__device__ __half g_xh [(size_t)NEXP * NTOK * DIM];   //  64 MB  x    fp16 [E][N][D]
__device__ __half g_w1t[(size_t)NEXP * HID * DIM];    // 128 MB  w1^T fp16 [E][H][D]
__device__ __half g_w2t[(size_t)NEXP * DIM * HID];    // 128 MB  w2^T fp16 [E][D][H]
__device__ __half g_hid[(size_t)NEXP * NTOK * HID];   // 256 MB  hidden fp16 [E][N][H]

// ---------------------------------------------------------------------------
// helpers
// ---------------------------------------------------------------------------
__device__ __forceinline__ uint32_t smem_u32(const void* p) {
    uint32_t a;
    asm("{ .reg .u64 t; cvta.to.shared.u64 t, %1; cvt.u32.u64 %0, t; }"
        : "=r"(a) : "l"(p));
    return a;
}

__device__ __forceinline__ void cp_async16(uint32_t smem, const void* gmem) {
    asm volatile("cp.async.cg.shared.global [%0], [%1], 16;\n"
                 :: "r"(smem), "l"(gmem));
}
__device__ __forceinline__ void cp_commit() {
    asm volatile("cp.async.commit_group;\n");
}
template <int N>
__device__ __forceinline__ void cp_wait() {
    asm volatile("cp.async.wait_group %0;\n" :: "n"(N));
}

__device__ __forceinline__ void ldsm_x4(uint32_t* r, uint32_t addr) {
    asm volatile("ldmatrix.sync.aligned.m8n8.x4.shared.b16 {%0,%1,%2,%3}, [%4];"
                 : "=r"(r[0]), "=r"(r[1]), "=r"(r[2]), "=r"(r[3]) : "r"(addr));
}

__device__ __forceinline__ void mma_f16(float* c, const uint32_t* a,
                                        uint32_t b0, uint32_t b1) {
    asm volatile(
        "mma.sync.aligned.m16n8k16.row.col.f32.f16.f16.f32 "
        "{%0,%1,%2,%3}, {%4,%5,%6,%7}, {%8,%9}, {%0,%1,%2,%3};"
        : "+f"(c[0]), "+f"(c[1]), "+f"(c[2]), "+f"(c[3])
        : "r"(a[0]), "r"(a[1]), "r"(a[2]), "r"(a[3]), "r"(b0), "r"(b1));
}

__device__ __forceinline__ float gelu_exact(float v) {
    return 0.5f * v * (1.0f + erff(v * 0.7071067811865476f));
}

// ---------------------------------------------------------------------------
// pre-pass kernels
// ---------------------------------------------------------------------------
__global__ void cvt_x_kernel(const float4* __restrict__ in, int n4) {
    int i = blockIdx.x * blockDim.x + threadIdx.x;
    if (i < n4) {
        float4 v = in[i];
        __half2 a = __floats2half2_rn(v.x, v.y);
        __half2 b = __floats2half2_rn(v.z, v.w);
        uint2 o;
        o.x = *reinterpret_cast<uint32_t*>(&a);
        o.y = *reinterpret_cast<uint32_t*>(&b);
        reinterpret_cast<uint2*>(g_xh)[i] = o;
    }
}

// in: [E][R][C] f32  ->  out: [E][C][R] f16
template <bool W1>
__global__ void transpose_cvt(const float* __restrict__ in, int R, int C) {
    __shared__ float tile[32][33];
    const int e = blockIdx.z;
    const int c0 = blockIdx.x * 32, r0 = blockIdx.y * 32;
    const float* src = in + (size_t)e * R * C;
    __half* dst = (W1 ? g_w1t : g_w2t) + (size_t)e * C * R;
    const int tx = threadIdx.x, ty = threadIdx.y;   // (32, 8)
    #pragma unroll
    for (int i = 0; i < 32; i += 8)
        tile[ty + i][tx] = src[(size_t)(r0 + ty + i) * C + c0 + tx];
    __syncthreads();
    #pragma unroll
    for (int i = 0; i < 32; i += 8)
        dst[(size_t)(c0 + ty + i) * R + r0 + tx] = __float2half_rn(tile[tx][ty + i]);
}

// ---------------------------------------------------------------------------
// fp16 HMMA grouped GEMM:  C[e] = op(A[e] @ B[e]^T + bias)
//   A: [E][M][K] fp16 K-major, B: [E][N][K] fp16 K-major
//   FIRST : A=g_xh,  B=g_w1t, C=g_hid (fp16, GELU)   M=2048 N=4096 K=1024
//   !FIRST: A=g_hid, B=g_w2t, C=out   (fp32, bias)   M=2048 N=1024 K=4096
// CTA 128x256, BK=64. 8 warps as 2(M) x 4(N), warp tile 64x64.
// 3-stage cp.async pipeline, one __syncthreads per k-iteration.
// Swizzle: byte offset row*128 + (kbyte ^ ((row&7)*16)).
// ---------------------------------------------------------------------------
#define BM 128
#define BN 256
#define BK 64
#define ASTAGE (BM * BK * 2)           // 16 KB
#define BSTAGE (BN * BK * 2)           // 32 KB
#define STAGEB (ASTAGE + BSTAGE)       // 48 KB
#define NSTAGE 3
#define SMEM_BYTES (NSTAGE * STAGEB + 1024)

template <bool FIRST>
__global__ void __launch_bounds__(256, 1)
moe_hmma(const float* __restrict__ bias, float* __restrict__ Cf)
{
    constexpr int N = FIRST ? HID : DIM;
    constexpr int K = FIRST ? DIM : HID;
    constexpr int KT = K / BK;

    extern __shared__ char smem_raw[];
    uint32_t sb = smem_u32(smem_raw);
    sb = (sb + 1023u) & ~1023u;

    const int tid  = threadIdx.x;
    const int lane = tid & 31;
    const int warp = tid >> 5;
    const int wr   = warp >> 2;          // 0..1 : 64-row band
    const int wc   = warp & 3;           // 0..3 : 64-col band

    const int e  = blockIdx.z;
    const int bm = blockIdx.y * BM;
    const int bn = blockIdx.x * BN;

    const __half* Abase = FIRST ? g_xh  : g_hid;
    const __half* Bbase = FIRST ? g_w1t : g_w2t;
    const char* Ag = reinterpret_cast<const char*>(Abase + ((size_t)e * NTOK + bm) * K);
    const char* Bg = reinterpret_cast<const char*>(Bbase + ((size_t)e * N    + bn) * K);

    // ---- loader constants: unit u = tid + 256*i, row=u>>3, cb=(u&7)*16 ----
    // swizzled smem offset = row*128 + (cb ^ ((row&7)*16))
    uint32_t lda_s[4], lda_g[4];         // A: 128 rows (4 units)
    uint32_t ldb_s[8], ldb_g[8];         // B: 256 rows (8 units)
    #pragma unroll
    for (int i = 0; i < 8; i++) {
        const int u   = tid + 256 * i;
        const int row = u >> 3;
        const int cb  = (u & 7) * 16;
        const uint32_t so = row * 128 + (cb ^ ((row & 7) * 16));
        const uint32_t go = row * (K * 2) + cb;
        if (i < 4) { lda_s[i] = so; lda_g[i] = go; }
        ldb_s[i] = so; ldb_g[i] = go;
    }

    auto load_tile = [&](int s, int kt) {
        const uint32_t ab = sb + s * STAGEB;
        const uint32_t bb = ab + ASTAGE;
        const uint32_t kb = (uint32_t)kt * (BK * 2);
        #pragma unroll
        for (int i = 0; i < 4; i++)
            cp_async16(ab + lda_s[i], Ag + lda_g[i] + kb);
        #pragma unroll
        for (int i = 0; i < 8; i++)
            cp_async16(bb + ldb_s[i], Bg + ldb_g[i] + kb);
    };

    // ---- ldmatrix per-lane constants ----
    const int grp  = lane >> 3;          // which 8x8 matrix this lane addresses
    const int lrow = lane & 7;
    const int xm   = lrow * 16;          // swizzle XOR for this lane's rows
    // A x4: (rows0-7,klo)(rows8-15,klo)(rows0-7,khi)(rows8-15,khi)
    const int a_row0 = wr * 64 + (grp & 1) * 8 + lrow;
    const int a_kh   = (grp >> 1) * 16;
    // B x4: (cols0-7,klo)(cols0-7,khi)(cols8-15,klo)(cols8-15,khi)
    const int b_row0 = wc * 64 + (grp >> 1) * 8 + lrow;
    const int b_kh   = (grp & 1) * 16;

    float acc[4][8][4];
    #pragma unroll
    for (int mt = 0; mt < 4; mt++)
        #pragma unroll
        for (int nt = 0; nt < 8; nt++)
            #pragma unroll
            for (int i = 0; i < 4; i++)
                acc[mt][nt][i] = 0.0f;

    // prologue: stage tiles 0, 1
    load_tile(0, 0); cp_commit();
    load_tile(1, 1); cp_commit();

    for (int kt = 0; kt < KT; kt++) {
        const int s = kt % NSTAGE;
        cp_wait<NSTAGE - 2>();           // stage kt resident
        __syncthreads();                 // all warps done with slot (kt-1)%3

        // prefetch tile kt+2 into slot (kt+2)%3 == (kt-1)%3 (just freed)
        if (kt + 2 < KT) load_tile((kt + 2) % NSTAGE, kt + 2);
        cp_commit();

        const uint32_t aS = sb + s * STAGEB;
        const uint32_t bS = aS + ASTAGE;

        #pragma unroll
        for (int kk = 0; kk < 4; kk++) {
            uint32_t af[4][4];
            #pragma unroll
            for (int mt = 0; mt < 4; mt++)
                ldsm_x4(af[mt], aS + (a_row0 + mt * 16) * 128 +
                                   ((kk * 32 + a_kh) ^ xm));
            uint32_t bf[4][4];
            #pragma unroll
            for (int p = 0; p < 4; p++)
                ldsm_x4(bf[p], bS + (b_row0 + p * 16) * 128 +
                                  ((kk * 32 + b_kh) ^ xm));
            #pragma unroll
            for (int mt = 0; mt < 4; mt++) {
                #pragma unroll
                for (int p = 0; p < 4; p++) {
                    mma_f16(acc[mt][2 * p],     af[mt], bf[p][0], bf[p][1]);
                    mma_f16(acc[mt][2 * p + 1], af[mt], bf[p][2], bf[p][3]);
                }
            }
        }
    }

    // ---- epilogue ----
    const int erow = bm + wr * 64 + (lane >> 2);
    const int ecol = bn + wc * 64 + (lane & 3) * 2;

    // hoist the 16 bias scalars this thread needs (8 nt-tiles x 2 cols)
    float bv[8][2];
    #pragma unroll
    for (int nt = 0; nt < 8; nt++) {
        bv[nt][0] = __ldg(bias + ecol + nt * 8);
        bv[nt][1] = __ldg(bias + ecol + nt * 8 + 1);
    }

    #pragma unroll
    for (int mt = 0; mt < 4; mt++) {
        #pragma unroll
        for (int nt = 0; nt < 8; nt++) {
            const int col = ecol + nt * 8;
            float v0 = acc[mt][nt][0] + bv[nt][0];
            float v1 = acc[mt][nt][1] + bv[nt][1];
            float v2 = acc[mt][nt][2] + bv[nt][0];
            float v3 = acc[mt][nt][3] + bv[nt][1];
            const int r0 = erow + mt * 16;
            if (FIRST) {
                v0 = gelu_exact(v0); v1 = gelu_exact(v1);
                v2 = gelu_exact(v2); v3 = gelu_exact(v3);
                __half2 h0 = __floats2half2_rn(v0, v1);
                __half2 h1 = __floats2half2_rn(v2, v3);
                __half* base = g_hid + (size_t)e * NTOK * N;
                *reinterpret_cast<__half2*>(base + (size_t)r0 * N + col) = h0;
                *reinterpret_cast<__half2*>(base + (size_t)(r0 + 8) * N + col) = h1;
            } else {
                float* base = Cf + (size_t)e * NTOK * N;
                *reinterpret_cast<float2*>(base + (size_t)r0 * N + col) =
                    make_float2(v0, v1);
                *reinterpret_cast<float2*>(base + (size_t)(r0 + 8) * N + col) =
                    make_float2(v2, v3);
            }
        }
    }
}

// ---------------------------------------------------------------------------
// launch
// ---------------------------------------------------------------------------
extern "C" void kernel_launch(void* const* d_in, const int* in_sizes, int n_in,
                              void* d_out, int out_size)
{
    const float* x  = (const float*)d_in[0];   // (E, N, D)
    const float* w1 = (const float*)d_in[1];   // (E, D, H)
    const float* w2 = (const float*)d_in[2];   // (E, H, D)
    const float* b1 = (const float*)d_in[3];   // (H)
    const float* b2 = (const float*)d_in[4];   // (D)
    float* out = (float*)d_out;                // (E, N, D)

    cudaFuncSetAttribute(moe_hmma<true>,
        cudaFuncAttributeMaxDynamicSharedMemorySize, SMEM_BYTES);
    cudaFuncSetAttribute(moe_hmma<false>,
        cudaFuncAttributeMaxDynamicSharedMemorySize, SMEM_BYTES);

    // pre-pass: fp16 conversions (+ weight transposes to K-major)
    const int n4 = (NEXP * NTOK * DIM) / 4;
    cvt_x_kernel<<<n4 / 256, 256>>>((const float4*)x, n4);
    transpose_cvt<true ><<<dim3(HID / 32, DIM / 32, NEXP), dim3(32, 8)>>>(w1, DIM, HID);
    transpose_cvt<false><<<dim3(DIM / 32, HID / 32, NEXP), dim3(32, 8)>>>(w2, HID, DIM);

    // layer 1: hidden = gelu(x @ w1 + b1)
    moe_hmma<true ><<<dim3(HID / BN, NTOK / BM, NEXP), 256, SMEM_BYTES>>>(b1, nullptr);
    // layer 2: out = hidden @ w2 + b2
    moe_hmma<false><<<dim3(DIM / BN, NTOK / BM, NEXP), 256, SMEM_BYTES>>>(b2, out);
}

// round 11
// speedup vs baseline: 1.0937x; 1.0937x over previous
#include <cuda_runtime.h>
#include <cuda_fp16.h>
#include <cstdint>
#include <cstddef>

// Problem constants.
#define NEXP 16
#define NTOK 2048
#define DIM  1024
#define HID  4096

// Static device scratch (no runtime allocation).
__device__ __half g_xh [(size_t)NEXP * NTOK * DIM];   //  64 MB  x    fp16 [E][N][D]
__device__ __half g_w1t[(size_t)NEXP * HID * DIM];    // 128 MB  w1^T fp16 [E][H][D]
__device__ __half g_w2t[(size_t)NEXP * DIM * HID];    // 128 MB  w2^T fp16 [E][D][H]
__device__ __half g_hid[(size_t)NEXP * NTOK * HID];   // 256 MB  hidden fp16 [E][N][H]

// ---------------------------------------------------------------------------
// helpers
// ---------------------------------------------------------------------------
__device__ __forceinline__ uint32_t smem_u32(const void* p) {
    uint32_t a;
    asm("{ .reg .u64 t; cvta.to.shared.u64 t, %1; cvt.u32.u64 %0, t; }"
        : "=r"(a) : "l"(p));
    return a;
}

__device__ __forceinline__ void cp_async16(uint32_t smem, const void* gmem) {
    asm volatile("cp.async.cg.shared.global [%0], [%1], 16;\n"
                 :: "r"(smem), "l"(gmem));
}
__device__ __forceinline__ void cp_commit() {
    asm volatile("cp.async.commit_group;\n");
}
template <int N>
__device__ __forceinline__ void cp_wait() {
    asm volatile("cp.async.wait_group %0;\n" :: "n"(N));
}

__device__ __forceinline__ void ldsm_x4(uint32_t* r, uint32_t addr) {
    asm volatile("ldmatrix.sync.aligned.m8n8.x4.shared.b16 {%0,%1,%2,%3}, [%4];"
                 : "=r"(r[0]), "=r"(r[1]), "=r"(r[2]), "=r"(r[3]) : "r"(addr));
}

__device__ __forceinline__ void mma_f16(float* c, const uint32_t* a,
                                        uint32_t b0, uint32_t b1) {
    asm volatile(
        "mma.sync.aligned.m16n8k16.row.col.f32.f16.f16.f32 "
        "{%0,%1,%2,%3}, {%4,%5,%6,%7}, {%8,%9}, {%0,%1,%2,%3};"
        : "+f"(c[0]), "+f"(c[1]), "+f"(c[2]), "+f"(c[3])
        : "r"(a[0]), "r"(a[1]), "r"(a[2]), "r"(a[3]), "r"(b0), "r"(b1));
}

__device__ __forceinline__ float gelu_exact(float v) {
    return 0.5f * v * (1.0f + erff(v * 0.7071067811865476f));
}

// ---------------------------------------------------------------------------
// pre-pass kernels
// ---------------------------------------------------------------------------
__global__ void cvt_x_kernel(const float4* __restrict__ in, int n4) {
    int i = blockIdx.x * blockDim.x + threadIdx.x;
    if (i < n4) {
        float4 v = in[i];
        __half2 a = __floats2half2_rn(v.x, v.y);
        __half2 b = __floats2half2_rn(v.z, v.w);
        uint2 o;
        o.x = *reinterpret_cast<uint32_t*>(&a);
        o.y = *reinterpret_cast<uint32_t*>(&b);
        reinterpret_cast<uint2*>(g_xh)[i] = o;
    }
}

// in: [E][R][C] f32  ->  out: [E][C][R] f16
template <bool W1>
__global__ void transpose_cvt(const float* __restrict__ in, int R, int C) {
    __shared__ float tile[32][33];
    const int e = blockIdx.z;
    const int c0 = blockIdx.x * 32, r0 = blockIdx.y * 32;
    const float* src = in + (size_t)e * R * C;
    __half* dst = (W1 ? g_w1t : g_w2t) + (size_t)e * C * R;
    const int tx = threadIdx.x, ty = threadIdx.y;   // (32, 8)
    #pragma unroll
    for (int i = 0; i < 32; i += 8)
        tile[ty + i][tx] = src[(size_t)(r0 + ty + i) * C + c0 + tx];
    __syncthreads();
    #pragma unroll
    for (int i = 0; i < 32; i += 8)
        dst[(size_t)(c0 + ty + i) * R + r0 + tx] = __float2half_rn(tile[tx][ty + i]);
}

// ---------------------------------------------------------------------------
// fp16 HMMA grouped GEMM:  C[e] = op(A[e] @ B[e]^T + bias)
//   A: [E][M][K] fp16 K-major, B: [E][N][K] fp16 K-major
//   FIRST : A=g_xh,  B=g_w1t, C=g_hid (fp16, GELU)   M=2048 N=4096 K=1024
//   !FIRST: A=g_hid, B=g_w2t, C=out   (fp32, bias)   M=2048 N=1024 K=4096
// CTA 128x128, BK=64. 8 warps as 2(M) x 4(N), warp tile 64x32. regs ~128.
// 3-stage cp.async pipeline, ONE __syncthreads per k-iteration, 2 CTAs/SM.
// Swizzle: byte offset row*128 + (kbyte ^ ((row&7)*16)).
// ---------------------------------------------------------------------------
#define BM 128
#define BN 128
#define BK 64
#define ASTAGE (BM * BK * 2)           // 16 KB
#define BSTAGE (BN * BK * 2)           // 16 KB
#define STAGEB (ASTAGE + BSTAGE)       // 32 KB
#define NSTAGE 3
#define SMEM_BYTES (NSTAGE * STAGEB + 1024)   // ~97 KB -> 2 CTAs/SM (194 < 228 KB)

template <bool FIRST>
__global__ void __launch_bounds__(256, 2)
moe_hmma(const float* __restrict__ bias, float* __restrict__ Cf)
{
    constexpr int N = FIRST ? HID : DIM;
    constexpr int K = FIRST ? DIM : HID;
    constexpr int KT = K / BK;

    extern __shared__ char smem_raw[];
    uint32_t sb = smem_u32(smem_raw);
    sb = (sb + 1023u) & ~1023u;

    const int tid  = threadIdx.x;
    const int lane = tid & 31;
    const int warp = tid >> 5;
    const int wr   = warp >> 2;          // 0..1 : 64-row band
    const int wc   = warp & 3;           // 0..3 : 32-col band

    const int e  = blockIdx.z;
    const int bm = blockIdx.y * BM;
    const int bn = blockIdx.x * BN;

    const __half* Abase = FIRST ? g_xh  : g_hid;
    const __half* Bbase = FIRST ? g_w1t : g_w2t;
    const char* Ag = reinterpret_cast<const char*>(Abase + ((size_t)e * NTOK + bm) * K);
    const char* Bg = reinterpret_cast<const char*>(Bbase + ((size_t)e * N    + bn) * K);

    // ---- loader constants: unit u = tid + 256*i, row=u>>3, cb=(u&7)*16 ----
    // swizzled smem offset = row*128 + (cb ^ ((row&7)*16))
    uint32_t ld_s[4], ld_g[4];           // 128 rows per operand = 4 units
    #pragma unroll
    for (int i = 0; i < 4; i++) {
        const int u   = tid + 256 * i;
        const int row = u >> 3;
        const int cb  = (u & 7) * 16;
        ld_s[i] = row * 128 + (cb ^ ((row & 7) * 16));
        ld_g[i] = row * (K * 2) + cb;
    }

    auto load_tile = [&](int s, int kt) {
        const uint32_t ab = sb + s * STAGEB;
        const uint32_t bb = ab + ASTAGE;
        const uint32_t kb = (uint32_t)kt * (BK * 2);
        #pragma unroll
        for (int i = 0; i < 4; i++)
            cp_async16(ab + ld_s[i], Ag + ld_g[i] + kb);
        #pragma unroll
        for (int i = 0; i < 4; i++)
            cp_async16(bb + ld_s[i], Bg + ld_g[i] + kb);
    };

    // ---- ldmatrix per-lane constants ----
    const int grp  = lane >> 3;
    const int lrow = lane & 7;
    const int xm   = lrow * 16;
    // A x4: (rows0-7,klo)(rows8-15,klo)(rows0-7,khi)(rows8-15,khi)
    const int a_row0 = wr * 64 + (grp & 1) * 8 + lrow;
    const int a_kh   = (grp >> 1) * 16;
    // B x4: (cols0-7,klo)(cols0-7,khi)(cols8-15,klo)(cols8-15,khi)
    const int b_row0 = wc * 32 + (grp >> 1) * 8 + lrow;
    const int b_kh   = (grp & 1) * 16;

    float acc[4][4][4];
    #pragma unroll
    for (int mt = 0; mt < 4; mt++)
        #pragma unroll
        for (int nt = 0; nt < 4; nt++)
            #pragma unroll
            for (int i = 0; i < 4; i++)
                acc[mt][nt][i] = 0.0f;

    // prologue: stage tiles 0, 1
    load_tile(0, 0); cp_commit();
    load_tile(1, 1); cp_commit();

    for (int kt = 0; kt < KT; kt++) {
        const int s = kt % NSTAGE;
        cp_wait<NSTAGE - 2>();           // stage kt resident
        __syncthreads();                 // all warps done with slot (kt-1)%3

        // prefetch tile kt+2 into slot (kt+2)%3 == (kt-1)%3 (just freed)
        if (kt + 2 < KT) load_tile((kt + 2) % NSTAGE, kt + 2);
        cp_commit();

        const uint32_t aS = sb + s * STAGEB;
        const uint32_t bS = aS + ASTAGE;

        #pragma unroll
        for (int kk = 0; kk < 4; kk++) {
            uint32_t af[4][4];
            #pragma unroll
            for (int mt = 0; mt < 4; mt++)
                ldsm_x4(af[mt], aS + (a_row0 + mt * 16) * 128 +
                                   ((kk * 32 + a_kh) ^ xm));
            uint32_t bf[2][4];
            #pragma unroll
            for (int p = 0; p < 2; p++)
                ldsm_x4(bf[p], bS + (b_row0 + p * 16) * 128 +
                                  ((kk * 32 + b_kh) ^ xm));
            #pragma unroll
            for (int mt = 0; mt < 4; mt++) {
                mma_f16(acc[mt][0], af[mt], bf[0][0], bf[0][1]);
                mma_f16(acc[mt][1], af[mt], bf[0][2], bf[0][3]);
                mma_f16(acc[mt][2], af[mt], bf[1][0], bf[1][1]);
                mma_f16(acc[mt][3], af[mt], bf[1][2], bf[1][3]);
            }
        }
    }

    // ---- epilogue ----
    const int erow = bm + wr * 64 + (lane >> 2);
    const int ecol = bn + wc * 32 + (lane & 3) * 2;

    // hoist the 8 bias scalars this thread needs (4 nt-tiles x 2 cols)
    float bv[4][2];
    #pragma unroll
    for (int nt = 0; nt < 4; nt++) {
        bv[nt][0] = __ldg(bias + ecol + nt * 8);
        bv[nt][1] = __ldg(bias + ecol + nt * 8 + 1);
    }

    #pragma unroll
    for (int mt = 0; mt < 4; mt++) {
        #pragma unroll
        for (int nt = 0; nt < 4; nt++) {
            const int col = ecol + nt * 8;
            float v0 = acc[mt][nt][0] + bv[nt][0];
            float v1 = acc[mt][nt][1] + bv[nt][1];
            float v2 = acc[mt][nt][2] + bv[nt][0];
            float v3 = acc[mt][nt][3] + bv[nt][1];
            const int r0 = erow + mt * 16;
            if (FIRST) {
                v0 = gelu_exact(v0); v1 = gelu_exact(v1);
                v2 = gelu_exact(v2); v3 = gelu_exact(v3);
                __half2 h0 = __floats2half2_rn(v0, v1);
                __half2 h1 = __floats2half2_rn(v2, v3);
                __half* base = g_hid + (size_t)e * NTOK * N;
                *reinterpret_cast<__half2*>(base + (size_t)r0 * N + col) = h0;
                *reinterpret_cast<__half2*>(base + (size_t)(r0 + 8) * N + col) = h1;
            } else {
                float* base = Cf + (size_t)e * NTOK * N;
                *reinterpret_cast<float2*>(base + (size_t)r0 * N + col) =
                    make_float2(v0, v1);
                *reinterpret_cast<float2*>(base + (size_t)(r0 + 8) * N + col) =
                    make_float2(v2, v3);
            }
        }
    }
}

// ---------------------------------------------------------------------------
// launch
// ---------------------------------------------------------------------------
extern "C" void kernel_launch(void* const* d_in, const int* in_sizes, int n_in,
                              void* d_out, int out_size)
{
    const float* x  = (const float*)d_in[0];   // (E, N, D)
    const float* w1 = (const float*)d_in[1];   // (E, D, H)
    const float* w2 = (const float*)d_in[2];   // (E, H, D)
    const float* b1 = (const float*)d_in[3];   // (H)
    const float* b2 = (const float*)d_in[4];   // (D)
    float* out = (float*)d_out;                // (E, N, D)

    cudaFuncSetAttribute(moe_hmma<true>,
        cudaFuncAttributeMaxDynamicSharedMemorySize, SMEM_BYTES);
    cudaFuncSetAttribute(moe_hmma<false>,
        cudaFuncAttributeMaxDynamicSharedMemorySize, SMEM_BYTES);

    // pre-pass: fp16 conversions (+ weight transposes to K-major)
    const int n4 = (NEXP * NTOK * DIM) / 4;
    cvt_x_kernel<<<n4 / 256, 256>>>((const float4*)x, n4);
    transpose_cvt<true ><<<dim3(HID / 32, DIM / 32, NEXP), dim3(32, 8)>>>(w1, DIM, HID);
    transpose_cvt<false><<<dim3(DIM / 32, HID / 32, NEXP), dim3(32, 8)>>>(w2, HID, DIM);

    // layer 1: hidden = gelu(x @ w1 + b1)
    moe_hmma<true ><<<dim3(HID / BN, NTOK / BM, NEXP), 256, SMEM_BYTES>>>(b1, nullptr);
    // layer 2: out = hidden @ w2 + b2
    moe_hmma<false><<<dim3(DIM / BN, NTOK / BM, NEXP), 256, SMEM_BYTES>>>(b2, out);
}

// round 14
// speedup vs baseline: 1.1354x; 1.0382x over previous
#include <cuda_runtime.h>
#include <cuda_fp16.h>
#include <cstdint>
#include <cstddef>

// Problem constants.
#define NEXP 16
#define NTOK 2048
#define DIM  1024
#define HID  4096

// Static device scratch (no runtime allocation).
__device__ __half g_xh [(size_t)NEXP * NTOK * DIM];   //  64 MB  x    fp16 [E][N][D]
__device__ __half g_w1t[(size_t)NEXP * HID * DIM];    // 128 MB  w1^T fp16 [E][H][D]
__device__ __half g_w2t[(size_t)NEXP * DIM * HID];    // 128 MB  w2^T fp16 [E][D][H]
__device__ __half g_hid[(size_t)NEXP * NTOK * HID];   // 256 MB  hidden fp16 [E][N][H]

// ---------------------------------------------------------------------------
// helpers
// ---------------------------------------------------------------------------
__device__ __forceinline__ uint32_t smem_u32(const void* p) {
    uint32_t a;
    asm("{ .reg .u64 t; cvta.to.shared.u64 t, %1; cvt.u32.u64 %0, t; }"
        : "=r"(a) : "l"(p));
    return a;
}

__device__ __forceinline__ void cp_async16(uint32_t smem, const void* gmem) {
    asm volatile("cp.async.cg.shared.global [%0], [%1], 16;\n"
                 :: "r"(smem), "l"(gmem));
}
__device__ __forceinline__ void cp_commit() {
    asm volatile("cp.async.commit_group;\n");
}
template <int N>
__device__ __forceinline__ void cp_wait() {
    asm volatile("cp.async.wait_group %0;\n" :: "n"(N));
}

__device__ __forceinline__ void ldsm_x4(uint32_t* r, uint32_t addr) {
    asm volatile("ldmatrix.sync.aligned.m8n8.x4.shared.b16 {%0,%1,%2,%3}, [%4];"
                 : "=r"(r[0]), "=r"(r[1]), "=r"(r[2]), "=r"(r[3]) : "r"(addr));
}

__device__ __forceinline__ void mma_f16(float* c, const uint32_t* a,
                                        uint32_t b0, uint32_t b1) {
    asm volatile(
        "mma.sync.aligned.m16n8k16.row.col.f32.f16.f16.f32 "
        "{%0,%1,%2,%3}, {%4,%5,%6,%7}, {%8,%9}, {%0,%1,%2,%3};"
        : "+f"(c[0]), "+f"(c[1]), "+f"(c[2]), "+f"(c[3])
        : "r"(a[0]), "r"(a[1]), "r"(a[2]), "r"(a[3]), "r"(b0), "r"(b1));
}

__device__ __forceinline__ float gelu_exact(float v) {
    return 0.5f * v * (1.0f + erff(v * 0.7071067811865476f));
}

// ---------------------------------------------------------------------------
// pre-pass kernels
// ---------------------------------------------------------------------------
__global__ void cvt_x_kernel(const float4* __restrict__ in, int n4) {
    int i = blockIdx.x * blockDim.x + threadIdx.x;
    if (i < n4) {
        float4 v = in[i];
        __half2 a = __floats2half2_rn(v.x, v.y);
        __half2 b = __floats2half2_rn(v.z, v.w);
        uint2 o;
        o.x = *reinterpret_cast<uint32_t*>(&a);
        o.y = *reinterpret_cast<uint32_t*>(&b);
        reinterpret_cast<uint2*>(g_xh)[i] = o;
    }
}

// in: [E][R][C] f32  ->  out: [E][C][R] f16
template <bool W1>
__global__ void transpose_cvt(const float* __restrict__ in, int R, int C) {
    __shared__ float tile[32][33];
    const int e = blockIdx.z;
    const int c0 = blockIdx.x * 32, r0 = blockIdx.y * 32;
    const float* src = in + (size_t)e * R * C;
    __half* dst = (W1 ? g_w1t : g_w2t) + (size_t)e * C * R;
    const int tx = threadIdx.x, ty = threadIdx.y;   // (32, 8)
    #pragma unroll
    for (int i = 0; i < 32; i += 8)
        tile[ty + i][tx] = src[(size_t)(r0 + ty + i) * C + c0 + tx];
    __syncthreads();
    #pragma unroll
    for (int i = 0; i < 32; i += 8)
        dst[(size_t)(c0 + ty + i) * R + r0 + tx] = __float2half_rn(tile[tx][ty + i]);
}

// ---------------------------------------------------------------------------
// fp16 HMMA grouped GEMM:  C[e] = op(A[e] @ B[e]^T + bias)
//   A: [E][M][K] fp16 K-major, B: [E][N][K] fp16 K-major
//   FIRST : A=g_xh,  B=g_w1t, C=g_hid (fp16, GELU)   M=2048 N=4096 K=1024
//   !FIRST: A=g_hid, B=g_w2t, C=out   (fp32, bias)   M=2048 N=1024 K=4096
// CTA 128x128, BK=64. *** 128 threads: 4 warps as 2x2, warp tile 64x64 ***
// (LDSM bytes/MAC = 0.0625, 33% lower than 64x32 tiling; ~210 regs/thread,
//  2 CTAs/SM resident: 256 thr x 210 regs = 54K < 64K RF.)
// 3-stage cp.async pipeline, ONE __syncthreads per k-iteration,
// loads issued AFTER the MMA block (R4 ordering).
// Swizzle: byte offset row*128 + (kbyte ^ ((row&7)*16)).
// ---------------------------------------------------------------------------
#define BM 128
#define BN 128
#define BK 64
#define ASTAGE (BM * BK * 2)           // 16 KB
#define BSTAGE (BN * BK * 2)           // 16 KB
#define STAGEB (ASTAGE + BSTAGE)       // 32 KB
#define NSTAGE 3
#define SMEM_BYTES (NSTAGE * STAGEB + 1024)   // ~97 KB -> 2 CTAs/SM

#define NTHREADS 128

template <bool FIRST>
__global__ void __launch_bounds__(NTHREADS, 2)
moe_hmma(const float* __restrict__ bias, float* __restrict__ Cf)
{
    constexpr int N = FIRST ? HID : DIM;
    constexpr int K = FIRST ? DIM : HID;
    constexpr int KT = K / BK;

    extern __shared__ char smem_raw[];
    uint32_t sb = smem_u32(smem_raw);
    sb = (sb + 1023u) & ~1023u;

    const int tid  = threadIdx.x;
    const int lane = tid & 31;
    const int warp = tid >> 5;           // 0..3
    const int wr   = warp >> 1;          // 0..1 : 64-row band
    const int wc   = warp & 1;           // 0..1 : 64-col band

    const int e  = blockIdx.z;
    const int bm = blockIdx.y * BM;
    const int bn = blockIdx.x * BN;

    const __half* Abase = FIRST ? g_xh  : g_hid;
    const __half* Bbase = FIRST ? g_w1t : g_w2t;
    const char* Ag = reinterpret_cast<const char*>(Abase + ((size_t)e * NTOK + bm) * K);
    const char* Bg = reinterpret_cast<const char*>(Bbase + ((size_t)e * N    + bn) * K);

    // ---- loader: 1024 16B units per operand, 128 threads -> 8 units each ----
    // unit u = tid + 128*i : row = u>>3, cb = (u&7)*16
    // swizzled smem offset = row*128 + (cb ^ ((row&7)*16))
    // To keep regs low, recompute offsets per call from tid (alu has slack).
    auto load_tile = [&](int s, int kt) {
        const uint32_t ab = sb + s * STAGEB;
        const uint32_t bb = ab + ASTAGE;
        const uint32_t kb = (uint32_t)kt * (BK * 2);
        #pragma unroll
        for (int i = 0; i < 8; i++) {
            const int u   = tid + NTHREADS * i;
            const int row = u >> 3;
            const int cb  = (u & 7) * 16;
            const uint32_t so = row * 128 + (cb ^ ((row & 7) * 16));
            const uint32_t go = row * (K * 2) + cb + kb;
            cp_async16(ab + so, Ag + go);
            cp_async16(bb + so, Bg + go);
        }
    };

    // ---- ldmatrix per-lane constants ----
    const int grp  = lane >> 3;
    const int lrow = lane & 7;
    const int xm   = lrow * 16;
    // A x4: (rows0-7,klo)(rows8-15,klo)(rows0-7,khi)(rows8-15,khi)
    const int a_row0 = wr * 64 + (grp & 1) * 8 + lrow;
    const int a_kh   = (grp >> 1) * 16;
    // B x4: (cols0-7,klo)(cols0-7,khi)(cols8-15,klo)(cols8-15,khi)
    const int b_row0 = wc * 64 + (grp >> 1) * 8 + lrow;
    const int b_kh   = (grp & 1) * 16;

    float acc[4][8][4];
    #pragma unroll
    for (int mt = 0; mt < 4; mt++)
        #pragma unroll
        for (int nt = 0; nt < 8; nt++)
            #pragma unroll
            for (int i = 0; i < 4; i++)
                acc[mt][nt][i] = 0.0f;

    // prologue: stage tiles 0, 1
    load_tile(0, 0); cp_commit();
    load_tile(1, 1); cp_commit();

    for (int kt = 0; kt < KT; kt++) {
        const int s = kt % NSTAGE;
        cp_wait<1>();                    // tile kt resident (kt+1 in flight)
        __syncthreads();                 // all 4 warps done with slot (kt-1)%3

        const uint32_t aS = sb + s * STAGEB;
        const uint32_t bS = aS + ASTAGE;

        #pragma unroll
        for (int kk = 0; kk < 4; kk++) {
            uint32_t af[4][4];
            #pragma unroll
            for (int mt = 0; mt < 4; mt++)
                ldsm_x4(af[mt], aS + (a_row0 + mt * 16) * 128 +
                                   ((kk * 32 + a_kh) ^ xm));
            uint32_t bf[4][4];
            #pragma unroll
            for (int p = 0; p < 4; p++)
                ldsm_x4(bf[p], bS + (b_row0 + p * 16) * 128 +
                                  ((kk * 32 + b_kh) ^ xm));
            #pragma unroll
            for (int mt = 0; mt < 4; mt++) {
                #pragma unroll
                for (int p = 0; p < 4; p++) {
                    mma_f16(acc[mt][2 * p],     af[mt], bf[p][0], bf[p][1]);
                    mma_f16(acc[mt][2 * p + 1], af[mt], bf[p][2], bf[p][3]);
                }
            }
        }

        // prefetch tile kt+2 into slot (kt+2)%3 == (kt-1)%3 (freed by the
        // barrier at the top of THIS iteration — safe to overwrite now)
        if (kt + 2 < KT) load_tile((kt + 2) % NSTAGE, kt + 2);
        cp_commit();
    }

    // ---- epilogue ----
    const int erow = bm + wr * 64 + (lane >> 2);
    const int ecol = bn + wc * 64 + (lane & 3) * 2;

    // hoist the 16 bias scalars this thread needs (8 nt-tiles x 2 cols)
    float bv[8][2];
    #pragma unroll
    for (int nt = 0; nt < 8; nt++) {
        bv[nt][0] = __ldg(bias + ecol + nt * 8);
        bv[nt][1] = __ldg(bias + ecol + nt * 8 + 1);
    }

    #pragma unroll
    for (int mt = 0; mt < 4; mt++) {
        #pragma unroll
        for (int nt = 0; nt < 8; nt++) {
            const int col = ecol + nt * 8;
            float v0 = acc[mt][nt][0] + bv[nt][0];
            float v1 = acc[mt][nt][1] + bv[nt][1];
            float v2 = acc[mt][nt][2] + bv[nt][0];
            float v3 = acc[mt][nt][3] + bv[nt][1];
            const int r0 = erow + mt * 16;
            if (FIRST) {
                v0 = gelu_exact(v0); v1 = gelu_exact(v1);
                v2 = gelu_exact(v2); v3 = gelu_exact(v3);
                __half2 h0 = __floats2half2_rn(v0, v1);
                __half2 h1 = __floats2half2_rn(v2, v3);
                __half* base = g_hid + (size_t)e * NTOK * N;
                *reinterpret_cast<__half2*>(base + (size_t)r0 * N + col) = h0;
                *reinterpret_cast<__half2*>(base + (size_t)(r0 + 8) * N + col) = h1;
            } else {
                float* base = Cf + (size_t)e * NTOK * N;
                *reinterpret_cast<float2*>(base + (size_t)r0 * N + col) =
                    make_float2(v0, v1);
                *reinterpret_cast<float2*>(base + (size_t)(r0 + 8) * N + col) =
                    make_float2(v2, v3);
            }
        }
    }
}

// ---------------------------------------------------------------------------
// launch
// ---------------------------------------------------------------------------
extern "C" void kernel_launch(void* const* d_in, const int* in_sizes, int n_in,
                              void* d_out, int out_size)
{
    const float* x  = (const float*)d_in[0];   // (E, N, D)
    const float* w1 = (const float*)d_in[1];   // (E, D, H)
    const float* w2 = (const float*)d_in[2];   // (E, H, D)
    const float* b1 = (const float*)d_in[3];   // (H)
    const float* b2 = (const float*)d_in[4];   // (D)
    float* out = (float*)d_out;                // (E, N, D)

    cudaFuncSetAttribute(moe_hmma<true>,
        cudaFuncAttributeMaxDynamicSharedMemorySize, SMEM_BYTES);
    cudaFuncSetAttribute(moe_hmma<false>,
        cudaFuncAttributeMaxDynamicSharedMemorySize, SMEM_BYTES);

    // pre-pass: fp16 conversions (+ weight transposes to K-major)
    const int n4 = (NEXP * NTOK * DIM) / 4;
    cvt_x_kernel<<<n4 / 256, 256>>>((const float4*)x, n4);
    transpose_cvt<true ><<<dim3(HID / 32, DIM / 32, NEXP), dim3(32, 8)>>>(w1, DIM, HID);
    transpose_cvt<false><<<dim3(DIM / 32, HID / 32, NEXP), dim3(32, 8)>>>(w2, HID, DIM);

    // layer 1: hidden = gelu(x @ w1 + b1)
    moe_hmma<true ><<<dim3(HID / BN, NTOK / BM, NEXP), NTHREADS, SMEM_BYTES>>>(b1, nullptr);
    // layer 2: out = hidden @ w2 + b2
    moe_hmma<false><<<dim3(DIM / BN, NTOK / BM, NEXP), NTHREADS, SMEM_BYTES>>>(b2, out);
}